// round 8
// baseline (speedup 1.0000x reference)
#include <cuda_runtime.h>
#include <cuda_fp16.h>
#include <cuda_bf16.h>
#include <cstdint>
#include <cstddef>

// ---------------------------------------------------------------------------
// QuantizedAttention (B=4, S=2048, H=1024)
//   quantize() == IEEE fp16 RN-even -> whole pipeline is an fp16 dataflow;
//   __float2half_rn is bit-exact vs the reference. QKV uses a bf16 hi/lo
//   split GEMM (hh+hl+lh, K_eff=3072) for exact fp16 rounding.
//   R8: 128x256 tiles (B-traffic halved; L2 off the queueing knee), 8 warps
//   of 64x64, NS=3 cp.async ring; V stored naturally, attn@V loads B via
//   ldmatrix.trans (no more 2-byte scatter epilogue).
// ---------------------------------------------------------------------------

namespace {
constexpr int Bn = 4, Sn = 2048, Hn = 1024, Mn = Bn * Sn;

constexpr int BM = 128, BN = 256, BK = 64;
constexpr int NS = 3;
constexpr int A_BYTES = BM * BK * 2;            // 16 KB
constexpr int B_BYTES = BN * BK * 2;            // 32 KB
constexpr int STAGE_BYTES = A_BYTES + B_BYTES;  // 48 KB
constexpr int SMEM_TOTAL = NS * STAGE_BYTES;    // 144 KB dynamic
}

// ---- scratch (device globals; allocation forbidden) -----------------------
__device__ __align__(16) uint16_t g_xhi[Mn * Hn];
__device__ __align__(16) uint16_t g_xlo[Mn * Hn];
__device__ __align__(16) uint16_t g_whi[3 * Hn * Hn];
__device__ __align__(16) uint16_t g_wlo[3 * Hn * Hn];
__device__ __align__(16) uint16_t g_q[Mn * Hn];       // fp16 [B,S,H]
__device__ __align__(16) uint16_t g_k[Mn * Hn];       // fp16 [B,S,H]
__device__ __align__(16) uint16_t g_v[Mn * Hn];       // fp16 [B,S,H] (natural)
__device__ __align__(16) uint16_t g_s[Bn * Sn * Sn];  // fp16 scores/probs

// ---- PTX helpers ----------------------------------------------------------
__device__ __forceinline__ uint32_t smem_u32(const void* p) {
    return (uint32_t)__cvta_generic_to_shared(p);
}
__device__ __forceinline__ void cp16(uint32_t s, const void* g) {
    asm volatile("cp.async.cg.shared.global [%0], [%1], 16;\n" :: "r"(s), "l"(g));
}
__device__ __forceinline__ void cp_commit() {
    asm volatile("cp.async.commit_group;\n" ::: "memory");
}
template <int N>
__device__ __forceinline__ void cp_wait() {
    asm volatile("cp.async.wait_group %0;\n" :: "n"(N) : "memory");
}
__device__ __forceinline__ void ldm_x4(uint32_t* r, uint32_t addr) {
    asm volatile("ldmatrix.sync.aligned.m8n8.x4.shared.b16 {%0,%1,%2,%3}, [%4];\n"
                 : "=r"(r[0]), "=r"(r[1]), "=r"(r[2]), "=r"(r[3]) : "r"(addr));
}
__device__ __forceinline__ void ldm_x4_t(uint32_t* r, uint32_t addr) {
    asm volatile("ldmatrix.sync.aligned.m8n8.x4.trans.shared.b16 {%0,%1,%2,%3}, [%4];\n"
                 : "=r"(r[0]), "=r"(r[1]), "=r"(r[2]), "=r"(r[3]) : "r"(addr));
}
template <bool BF16>
__device__ __forceinline__ void mma_16816(float* d, const uint32_t* a, const uint32_t* b) {
    if constexpr (BF16) {
        asm volatile(
            "mma.sync.aligned.m16n8k16.row.col.f32.bf16.bf16.f32 "
            "{%0,%1,%2,%3},{%4,%5,%6,%7},{%8,%9},{%0,%1,%2,%3};\n"
            : "+f"(d[0]), "+f"(d[1]), "+f"(d[2]), "+f"(d[3])
            : "r"(a[0]), "r"(a[1]), "r"(a[2]), "r"(a[3]), "r"(b[0]), "r"(b[1]));
    } else {
        asm volatile(
            "mma.sync.aligned.m16n8k16.row.col.f32.f16.f16.f32 "
            "{%0,%1,%2,%3},{%4,%5,%6,%7},{%8,%9},{%0,%1,%2,%3};\n"
            : "+f"(d[0]), "+f"(d[1]), "+f"(d[2]), "+f"(d[3])
            : "r"(a[0]), "r"(a[1]), "r"(a[2]), "r"(a[3]), "r"(b[0]), "r"(b[1]));
    }
}

// ---- split f32 -> bf16 hi/lo ----------------------------------------------
__global__ void k_split(const float* __restrict__ src, int which, int n) {
    int i = blockIdx.x * 256 + threadIdx.x;
    if (i >= n) return;
    uint16_t* hi;
    uint16_t* lo;
    if (which == 0) { hi = g_xhi; lo = g_xlo; }
    else {
        int off = (which - 1) * Hn * Hn;
        hi = g_whi + off; lo = g_wlo + off;
    }
    float v = src[i];
    __nv_bfloat16 h = __float2bfloat16(v);
    __nv_bfloat16 l = __float2bfloat16(v - __bfloat162float(h));
    hi[i] = __bfloat16_as_ushort(h);
    lo[i] = __bfloat16_as_ushort(l);
}

// ---- 128x256x64, 3-stage cp.async, mma.sync GEMM --------------------------
// MODE 0: QKV  (bf16 split, K_eff=3072: hh|hl|lh segments of 1024)
// MODE 1: scores = Q K^T * (1/32) -> fp16 g_s   (per batch)
// MODE 2: out    = attn @ V -> f32 d_out (B from row-major V via ldm.trans)
template <int MODE>
__global__ __launch_bounds__(256, 1) void gemm_k(
    const float* __restrict__ bq, const float* __restrict__ bk,
    const float* __restrict__ bv, float* __restrict__ outF) {

    constexpr bool BF = (MODE == 0);
    constexpr int KT = (MODE == 0) ? 48 : ((MODE == 1) ? 16 : 32);  // K/64

    extern __shared__ __align__(128) uint16_t sh[];

    const int tid  = threadIdx.x;
    const int warp = tid >> 5;
    const int lane = tid & 31;
    const int wm = warp >> 2;             // 0..1  (64-row warp tiles)
    const int wn = warp & 3;              // 0..3  (64-col warp tiles)
    const int m0 = blockIdx.y * BM;
    const int n0 = blockIdx.x * BN;
    const int bz = blockIdx.z;

    const uint32_t shBase = smem_u32(sh);

    auto load_stage = [&](int j) {
        const uint32_t sA = shBase + (uint32_t)(j % NS) * STAGE_BYTES;
        const uint32_t sB = sA + A_BYTES;
        const uint16_t* ap;
        const uint16_t* bp;
        int kin, lda;
        if constexpr (MODE == 0) {
            int seg = j >> 4;             // 0:hh 1:hl 2:lh (16 steps each)
            kin = (j & 15) * BK;
            ap = (seg < 2) ? g_xhi : g_xlo;
            bp = (seg == 1) ? g_wlo : g_whi;
            lda = Hn;
        } else if constexpr (MODE == 1) {
            kin = j * BK;
            ap = g_q + (size_t)bz * Sn * Hn;
            bp = g_k + (size_t)bz * Sn * Hn;
            lda = Hn;
        } else {
            kin = j * BK;
            ap = g_s + (size_t)bz * Sn * Sn;
            bp = g_v + (size_t)bz * Sn * Hn;
            lda = Sn;
        }
        // A: 128 rows x 8 chunks(16B), 128B rows, XOR swizzle
#pragma unroll
        for (int it = 0; it < 4; it++) {
            int i = tid + it * 256;
            int row = i >> 3, c = i & 7;
            cp16(sA + (uint32_t)(row * 128 + ((c ^ (row & 7)) << 4)),
                 ap + (size_t)(m0 + row) * lda + kin + c * 8);
        }
        if constexpr (MODE != 2) {
            // B: 256 n-rows x 8 chunks (k-contig), 128B rows
#pragma unroll
            for (int it = 0; it < 8; it++) {
                int i = tid + it * 256;
                int row = i >> 3, c = i & 7;
                cp16(sB + (uint32_t)(row * 128 + ((c ^ (row & 7)) << 4)),
                     bp + (size_t)(n0 + row) * Hn + kin + c * 8);
            }
        } else {
            // B: 64 k-rows x 32 chunks (n-contig, row=t), 512B rows
#pragma unroll
            for (int it = 0; it < 8; it++) {
                int i = tid + it * 256;
                int row = i >> 5, c = i & 31;
                cp16(sB + (uint32_t)(row * 512 + ((c ^ (row & 7)) << 4)),
                     bp + (size_t)(kin + row) * Hn + n0 + c * 8);
            }
        }
    };

    float acc[4][8][4];
#pragma unroll
    for (int a = 0; a < 4; a++)
#pragma unroll
        for (int b2 = 0; b2 < 8; b2++)
#pragma unroll
            for (int e = 0; e < 4; e++) acc[a][b2][e] = 0.f;

    load_stage(0); cp_commit();
    load_stage(1); cp_commit();

    for (int j = 0; j < KT; ++j) {
        cp_wait<1>();
        __syncthreads();
        if (j + 2 < KT) load_stage(j + 2);
        cp_commit();

        const uint32_t aS = shBase + (uint32_t)(j % NS) * STAGE_BYTES;
        const uint32_t bS = aS + A_BYTES;

#pragma unroll
        for (int kc = 0; kc < 4; kc++) {
            const int lc = kc * 2;
            uint32_t afr[4][4], bfr[4][4];
#pragma unroll
            for (int mi = 0; mi < 4; mi++) {
                int row = wm * 64 + mi * 16 + (lane & 15);
                int ch  = (lc + (lane >> 4)) ^ (row & 7);
                ldm_x4(afr[mi], aS + (uint32_t)(row * 128 + (ch << 4)));
            }
#pragma unroll
            for (int nj = 0; nj < 4; nj++) {
                if constexpr (MODE != 2) {
                    int nrow = wn * 64 + nj * 16 + ((lane & 7) + ((lane >> 4) << 3));
                    int ch   = (lc + ((lane >> 3) & 1)) ^ (nrow & 7);
                    ldm_x4(bfr[nj], bS + (uint32_t)(nrow * 128 + (ch << 4)));
                } else {
                    int krow = kc * 16 + (lane & 15);
                    int c    = ((wn * 64 + nj * 16) >> 3) + (lane >> 4);
                    ldm_x4_t(bfr[nj],
                             bS + (uint32_t)(krow * 512 + ((c ^ (krow & 7)) << 4)));
                }
            }
#pragma unroll
            for (int mi = 0; mi < 4; mi++)
#pragma unroll
                for (int ni = 0; ni < 8; ni++)
                    mma_16816<BF>(acc[mi][ni], afr[mi], &bfr[ni >> 1][(ni & 1) * 2]);
        }
    }

    // ---- epilogue ----
#pragma unroll
    for (int mi = 0; mi < 4; mi++)
#pragma unroll
        for (int ni = 0; ni < 8; ni++)
#pragma unroll
            for (int eh = 0; eh < 2; eh++) {
                const int r = m0 + wm * 64 + mi * 16 + (lane >> 2) + eh * 8;
                const int c = n0 + wn * 64 + ni * 8 + ((lane & 3) << 1);
                float y0 = acc[mi][ni][eh * 2];
                float y1 = acc[mi][ni][eh * 2 + 1];
                if constexpr (MODE == 0) {
                    const int which = blockIdx.x >> 2;   // 0:Q 1:K 2:V
                    const int o = c & (Hn - 1);
                    const float* bias = (which == 0) ? bq : ((which == 1) ? bk : bv);
                    uint16_t* base = (which == 0) ? g_q : ((which == 1) ? g_k : g_v);
                    __half2 h2 = __floats2half2_rn(y0 + __ldg(&bias[o]),
                                                   y1 + __ldg(&bias[o + 1]));
                    *reinterpret_cast<uint32_t*>(base + (size_t)r * Hn + o) =
                        *reinterpret_cast<uint32_t*>(&h2);
                } else if constexpr (MODE == 1) {
                    __half2 h2 = __floats2half2_rn(y0 * 0.03125f, y1 * 0.03125f);
                    *reinterpret_cast<uint32_t*>(
                        g_s + (size_t)bz * Sn * Sn + (size_t)r * Sn + c) =
                        *reinterpret_cast<uint32_t*>(&h2);
                } else {
                    float2 f2 = make_float2(y0, y1);
                    *reinterpret_cast<float2*>(
                        outF + ((size_t)bz * Sn + r) * Hn + c) = f2;
                }
            }
}

// ---- row softmax over 2048 fp16 scores, fp16-RN in-place ------------------
__global__ void k_softmax(void) {
    const int row = blockIdx.x;
    const int tid = threadIdx.x;
    uint32_t* p32 = reinterpret_cast<uint32_t*>(g_s + (size_t)row * Sn);

    float v[8];
    float mx = -3.4e38f;
#pragma unroll
    for (int i = 0; i < 4; i++) {
        uint32_t u = p32[tid + i * 256];
        float a = __half2float(__ushort_as_half((unsigned short)(u & 0xFFFFu)));
        float b = __half2float(__ushort_as_half((unsigned short)(u >> 16)));
        v[2 * i] = a; v[2 * i + 1] = b;
        mx = fmaxf(mx, fmaxf(a, b));
    }
    __shared__ float red[256];
    red[tid] = mx; __syncthreads();
#pragma unroll
    for (int s = 128; s > 0; s >>= 1) {
        if (tid < s) red[tid] = fmaxf(red[tid], red[tid + s]);
        __syncthreads();
    }
    mx = red[0];
    __syncthreads();

    float sum = 0.f;
#pragma unroll
    for (int i = 0; i < 8; i++) { v[i] = expf(v[i] - mx); sum += v[i]; }
    red[tid] = sum; __syncthreads();
#pragma unroll
    for (int s = 128; s > 0; s >>= 1) {
        if (tid < s) red[tid] += red[tid + s];
        __syncthreads();
    }
    sum = red[0];

#pragma unroll
    for (int i = 0; i < 4; i++) {
        uint32_t lo = (uint32_t)__half_as_ushort(__float2half_rn(v[2 * i] / sum));
        uint32_t hi = (uint32_t)__half_as_ushort(__float2half_rn(v[2 * i + 1] / sum));
        p32[tid + i * 256] = lo | (hi << 16);
    }
}

// ---------------------------------------------------------------------------
extern "C" void kernel_launch(void* const* d_in, const int* in_sizes, int n_in,
                              void* d_out, int out_size) {
    (void)in_sizes; (void)n_in; (void)out_size;
    const float* x  = (const float*)d_in[0];
    const float* Wq = (const float*)d_in[1];
    const float* bq = (const float*)d_in[2];
    const float* Wk = (const float*)d_in[3];
    const float* bk = (const float*)d_in[4];
    const float* Wv = (const float*)d_in[5];
    const float* bv = (const float*)d_in[6];
    float* out = (float*)d_out;

    cudaFuncSetAttribute(gemm_k<0>, cudaFuncAttributeMaxDynamicSharedMemorySize, SMEM_TOTAL);
    cudaFuncSetAttribute(gemm_k<1>, cudaFuncAttributeMaxDynamicSharedMemorySize, SMEM_TOTAL);
    cudaFuncSetAttribute(gemm_k<2>, cudaFuncAttributeMaxDynamicSharedMemorySize, SMEM_TOTAL);

    // 1) bf16 hi/lo splits
    k_split<<<(Mn * Hn + 255) / 256, 256>>>(x,  0, Mn * Hn);
    k_split<<<(Hn * Hn + 255) / 256, 256>>>(Wq, 1, Hn * Hn);
    k_split<<<(Hn * Hn + 255) / 256, 256>>>(Wk, 2, Hn * Hn);
    k_split<<<(Hn * Hn + 255) / 256, 256>>>(Wv, 3, Hn * Hn);

    // 2) fused QKV projection + bias + fp16 quantize (Q,K,V all [B,S,H])
    gemm_k<0><<<dim3(3 * Hn / BN, Mn / BM, 1), 256, SMEM_TOTAL>>>(bq, bk, bv, nullptr);

    // 3) scores = Q K^T / 32, fp16 quantize
    gemm_k<1><<<dim3(Sn / BN, Sn / BM, Bn), 256, SMEM_TOTAL>>>(nullptr, nullptr, nullptr, nullptr);

    // 4) softmax rows, fp16 quantize (in-place)
    k_softmax<<<Mn, 256>>>();

    // 5) out = attn @ V (f32), B operand from row-major V via ldmatrix.trans
    gemm_k<2><<<dim3(Hn / BN, Sn / BM, Bn), 256, SMEM_TOTAL>>>(nullptr, nullptr, nullptr, out);
}

// round 9
// speedup vs baseline: 1.0211x; 1.0211x over previous
#include <cuda_runtime.h>
#include <cuda_fp16.h>
#include <cuda_bf16.h>
#include <cstdint>
#include <cstddef>

// ---------------------------------------------------------------------------
// QuantizedAttention (B=4, S=2048, H=1024)
//   quantize() == IEEE fp16 RN-even -> whole pipeline is an fp16 dataflow;
//   __float2half_rn is bit-exact vs the reference. QKV uses a bf16 hi/lo
//   split GEMM (hh+hl+lh, K_eff=3072) for exact fp16 rounding.
//   R9: 128x256x64 tile, NS=3 ring, but 512 threads (16 warps/SM, warp tile
//   32x64, acc=64 regs) -> R8's halved L2 traffic + R7's latency hiding.
// ---------------------------------------------------------------------------

namespace {
constexpr int Bn = 4, Sn = 2048, Hn = 1024, Mn = Bn * Sn;

constexpr int BM = 128, BN = 256, BK = 64;
constexpr int NS = 3;
constexpr int A_BYTES = BM * BK * 2;            // 16 KB
constexpr int B_BYTES = BN * BK * 2;            // 32 KB
constexpr int STAGE_BYTES = A_BYTES + B_BYTES;  // 48 KB
constexpr int SMEM_TOTAL = NS * STAGE_BYTES;    // 144 KB dynamic
constexpr int NT = 512;                          // threads per CTA
}

// ---- scratch (device globals; allocation forbidden) -----------------------
__device__ __align__(16) uint16_t g_xhi[Mn * Hn];
__device__ __align__(16) uint16_t g_xlo[Mn * Hn];
__device__ __align__(16) uint16_t g_whi[3 * Hn * Hn];
__device__ __align__(16) uint16_t g_wlo[3 * Hn * Hn];
__device__ __align__(16) uint16_t g_q[Mn * Hn];       // fp16 [B,S,H]
__device__ __align__(16) uint16_t g_k[Mn * Hn];       // fp16 [B,S,H]
__device__ __align__(16) uint16_t g_v[Mn * Hn];       // fp16 [B,S,H]
__device__ __align__(16) uint16_t g_s[Bn * Sn * Sn];  // fp16 scores/probs

// ---- PTX helpers ----------------------------------------------------------
__device__ __forceinline__ uint32_t smem_u32(const void* p) {
    return (uint32_t)__cvta_generic_to_shared(p);
}
__device__ __forceinline__ void cp16(uint32_t s, const void* g) {
    asm volatile("cp.async.cg.shared.global [%0], [%1], 16;\n" :: "r"(s), "l"(g));
}
__device__ __forceinline__ void cp_commit() {
    asm volatile("cp.async.commit_group;\n" ::: "memory");
}
template <int N>
__device__ __forceinline__ void cp_wait() {
    asm volatile("cp.async.wait_group %0;\n" :: "n"(N) : "memory");
}
__device__ __forceinline__ void ldm_x4(uint32_t* r, uint32_t addr) {
    asm volatile("ldmatrix.sync.aligned.m8n8.x4.shared.b16 {%0,%1,%2,%3}, [%4];\n"
                 : "=r"(r[0]), "=r"(r[1]), "=r"(r[2]), "=r"(r[3]) : "r"(addr));
}
__device__ __forceinline__ void ldm_x4_t(uint32_t* r, uint32_t addr) {
    asm volatile("ldmatrix.sync.aligned.m8n8.x4.trans.shared.b16 {%0,%1,%2,%3}, [%4];\n"
                 : "=r"(r[0]), "=r"(r[1]), "=r"(r[2]), "=r"(r[3]) : "r"(addr));
}
template <bool BF16>
__device__ __forceinline__ void mma_16816(float* d, const uint32_t* a, const uint32_t* b) {
    if constexpr (BF16) {
        asm volatile(
            "mma.sync.aligned.m16n8k16.row.col.f32.bf16.bf16.f32 "
            "{%0,%1,%2,%3},{%4,%5,%6,%7},{%8,%9},{%0,%1,%2,%3};\n"
            : "+f"(d[0]), "+f"(d[1]), "+f"(d[2]), "+f"(d[3])
            : "r"(a[0]), "r"(a[1]), "r"(a[2]), "r"(a[3]), "r"(b[0]), "r"(b[1]));
    } else {
        asm volatile(
            "mma.sync.aligned.m16n8k16.row.col.f32.f16.f16.f32 "
            "{%0,%1,%2,%3},{%4,%5,%6,%7},{%8,%9},{%0,%1,%2,%3};\n"
            : "+f"(d[0]), "+f"(d[1]), "+f"(d[2]), "+f"(d[3])
            : "r"(a[0]), "r"(a[1]), "r"(a[2]), "r"(a[3]), "r"(b[0]), "r"(b[1]));
    }
}

// ---- split f32 -> bf16 hi/lo ----------------------------------------------
__global__ void k_split(const float* __restrict__ src, int which, int n) {
    int i = blockIdx.x * 256 + threadIdx.x;
    if (i >= n) return;
    uint16_t* hi;
    uint16_t* lo;
    if (which == 0) { hi = g_xhi; lo = g_xlo; }
    else {
        int off = (which - 1) * Hn * Hn;
        hi = g_whi + off; lo = g_wlo + off;
    }
    float v = src[i];
    __nv_bfloat16 h = __float2bfloat16(v);
    __nv_bfloat16 l = __float2bfloat16(v - __bfloat162float(h));
    hi[i] = __bfloat16_as_ushort(h);
    lo[i] = __bfloat16_as_ushort(l);
}

// ---- 128x256x64, 3-stage cp.async, mma.sync GEMM, 512 threads -------------
// MODE 0: QKV  (bf16 split, K_eff=3072: hh|hl|lh segments of 1024)
// MODE 1: scores = Q K^T * (1/32) -> fp16 g_s   (per batch)
// MODE 2: out    = attn @ V -> f32 d_out (B from row-major V via ldm.trans)
template <int MODE>
__global__ __launch_bounds__(NT, 1) void gemm_k(
    const float* __restrict__ bq, const float* __restrict__ bk,
    const float* __restrict__ bv, float* __restrict__ outF) {

    constexpr bool BF = (MODE == 0);
    constexpr int KT = (MODE == 0) ? 48 : ((MODE == 1) ? 16 : 32);  // K/64

    extern __shared__ __align__(128) uint16_t sh[];

    const int tid  = threadIdx.x;
    const int warp = tid >> 5;
    const int lane = tid & 31;
    const int wm = warp >> 2;             // 0..3  (32-row warp tiles)
    const int wn = warp & 3;              // 0..3  (64-col warp tiles)
    const int m0 = blockIdx.y * BM;
    const int n0 = blockIdx.x * BN;
    const int bz = blockIdx.z;

    const uint32_t shBase = smem_u32(sh);

    auto load_stage = [&](int j) {
        const uint32_t sA = shBase + (uint32_t)(j % NS) * STAGE_BYTES;
        const uint32_t sB = sA + A_BYTES;
        const uint16_t* ap;
        const uint16_t* bp;
        int kin, lda;
        if constexpr (MODE == 0) {
            int seg = j >> 4;             // 0:hh 1:hl 2:lh (16 steps each)
            kin = (j & 15) * BK;
            ap = (seg < 2) ? g_xhi : g_xlo;
            bp = (seg == 1) ? g_wlo : g_whi;
            lda = Hn;
        } else if constexpr (MODE == 1) {
            kin = j * BK;
            ap = g_q + (size_t)bz * Sn * Hn;
            bp = g_k + (size_t)bz * Sn * Hn;
            lda = Hn;
        } else {
            kin = j * BK;
            ap = g_s + (size_t)bz * Sn * Sn;
            bp = g_v + (size_t)bz * Sn * Hn;
            lda = Sn;
        }
        // A: 128 rows x 8 chunks(16B), 128B rows, XOR swizzle -> 1024 chunks
#pragma unroll
        for (int it = 0; it < 2; it++) {
            int i = tid + it * NT;
            int row = i >> 3, c = i & 7;
            cp16(sA + (uint32_t)(row * 128 + ((c ^ (row & 7)) << 4)),
                 ap + (size_t)(m0 + row) * lda + kin + c * 8);
        }
        if constexpr (MODE != 2) {
            // B: 256 n-rows x 8 chunks (k-contig), 128B rows -> 2048 chunks
#pragma unroll
            for (int it = 0; it < 4; it++) {
                int i = tid + it * NT;
                int row = i >> 3, c = i & 7;
                cp16(sB + (uint32_t)(row * 128 + ((c ^ (row & 7)) << 4)),
                     bp + (size_t)(n0 + row) * Hn + kin + c * 8);
            }
        } else {
            // B: 64 k-rows x 32 chunks (n-contig), 512B rows -> 2048 chunks
#pragma unroll
            for (int it = 0; it < 4; it++) {
                int i = tid + it * NT;
                int row = i >> 5, c = i & 31;
                cp16(sB + (uint32_t)(row * 512 + ((c ^ (row & 7)) << 4)),
                     bp + (size_t)(kin + row) * Hn + n0 + c * 8);
            }
        }
    };

    float acc[2][8][4];
#pragma unroll
    for (int a = 0; a < 2; a++)
#pragma unroll
        for (int b2 = 0; b2 < 8; b2++)
#pragma unroll
            for (int e = 0; e < 4; e++) acc[a][b2][e] = 0.f;

    load_stage(0); cp_commit();
    load_stage(1); cp_commit();

    for (int j = 0; j < KT; ++j) {
        cp_wait<1>();
        __syncthreads();
        if (j + 2 < KT) load_stage(j + 2);
        cp_commit();

        const uint32_t aS = shBase + (uint32_t)(j % NS) * STAGE_BYTES;
        const uint32_t bS = aS + A_BYTES;

#pragma unroll
        for (int kc = 0; kc < 4; kc++) {
            const int lc = kc * 2;
            uint32_t afr[2][4], bfr[4][4];
#pragma unroll
            for (int mi = 0; mi < 2; mi++) {
                int row = wm * 32 + mi * 16 + (lane & 15);
                int ch  = (lc + (lane >> 4)) ^ (row & 7);
                ldm_x4(afr[mi], aS + (uint32_t)(row * 128 + (ch << 4)));
            }
#pragma unroll
            for (int nj = 0; nj < 4; nj++) {
                if constexpr (MODE != 2) {
                    int nrow = wn * 64 + nj * 16 + ((lane & 7) + ((lane >> 4) << 3));
                    int ch   = (lc + ((lane >> 3) & 1)) ^ (nrow & 7);
                    ldm_x4(bfr[nj], bS + (uint32_t)(nrow * 128 + (ch << 4)));
                } else {
                    int krow = kc * 16 + (lane & 15);
                    int c    = ((wn * 64 + nj * 16) >> 3) + (lane >> 4);
                    ldm_x4_t(bfr[nj],
                             bS + (uint32_t)(krow * 512 + ((c ^ (krow & 7)) << 4)));
                }
            }
#pragma unroll
            for (int mi = 0; mi < 2; mi++)
#pragma unroll
                for (int ni = 0; ni < 8; ni++)
                    mma_16816<BF>(acc[mi][ni], afr[mi], &bfr[ni >> 1][(ni & 1) * 2]);
        }
    }

    // ---- epilogue ----
#pragma unroll
    for (int mi = 0; mi < 2; mi++)
#pragma unroll
        for (int ni = 0; ni < 8; ni++)
#pragma unroll
            for (int eh = 0; eh < 2; eh++) {
                const int r = m0 + wm * 32 + mi * 16 + (lane >> 2) + eh * 8;
                const int c = n0 + wn * 64 + ni * 8 + ((lane & 3) << 1);
                float y0 = acc[mi][ni][eh * 2];
                float y1 = acc[mi][ni][eh * 2 + 1];
                if constexpr (MODE == 0) {
                    const int which = blockIdx.x >> 2;   // 0:Q 1:K 2:V
                    const int o = c & (Hn - 1);
                    const float* bias = (which == 0) ? bq : ((which == 1) ? bk : bv);
                    uint16_t* base = (which == 0) ? g_q : ((which == 1) ? g_k : g_v);
                    __half2 h2 = __floats2half2_rn(y0 + __ldg(&bias[o]),
                                                   y1 + __ldg(&bias[o + 1]));
                    *reinterpret_cast<uint32_t*>(base + (size_t)r * Hn + o) =
                        *reinterpret_cast<uint32_t*>(&h2);
                } else if constexpr (MODE == 1) {
                    __half2 h2 = __floats2half2_rn(y0 * 0.03125f, y1 * 0.03125f);
                    *reinterpret_cast<uint32_t*>(
                        g_s + (size_t)bz * Sn * Sn + (size_t)r * Sn + c) =
                        *reinterpret_cast<uint32_t*>(&h2);
                } else {
                    float2 f2 = make_float2(y0, y1);
                    *reinterpret_cast<float2*>(
                        outF + ((size_t)bz * Sn + r) * Hn + c) = f2;
                }
            }
}

// ---- row softmax over 2048 fp16 scores, fp16-RN in-place ------------------
__global__ void k_softmax(void) {
    const int row = blockIdx.x;
    const int tid = threadIdx.x;
    uint32_t* p32 = reinterpret_cast<uint32_t*>(g_s + (size_t)row * Sn);

    float v[8];
    float mx = -3.4e38f;
#pragma unroll
    for (int i = 0; i < 4; i++) {
        uint32_t u = p32[tid + i * 256];
        float a = __half2float(__ushort_as_half((unsigned short)(u & 0xFFFFu)));
        float b = __half2float(__ushort_as_half((unsigned short)(u >> 16)));
        v[2 * i] = a; v[2 * i + 1] = b;
        mx = fmaxf(mx, fmaxf(a, b));
    }
    __shared__ float red[256];
    red[tid] = mx; __syncthreads();
#pragma unroll
    for (int s = 128; s > 0; s >>= 1) {
        if (tid < s) red[tid] = fmaxf(red[tid], red[tid + s]);
        __syncthreads();
    }
    mx = red[0];
    __syncthreads();

    float sum = 0.f;
#pragma unroll
    for (int i = 0; i < 8; i++) { v[i] = expf(v[i] - mx); sum += v[i]; }
    red[tid] = sum; __syncthreads();
#pragma unroll
    for (int s = 128; s > 0; s >>= 1) {
        if (tid < s) red[tid] += red[tid + s];
        __syncthreads();
    }
    sum = red[0];

#pragma unroll
    for (int i = 0; i < 4; i++) {
        uint32_t lo = (uint32_t)__half_as_ushort(__float2half_rn(v[2 * i] / sum));
        uint32_t hi = (uint32_t)__half_as_ushort(__float2half_rn(v[2 * i + 1] / sum));
        p32[tid + i * 256] = lo | (hi << 16);
    }
}

// ---------------------------------------------------------------------------
extern "C" void kernel_launch(void* const* d_in, const int* in_sizes, int n_in,
                              void* d_out, int out_size) {
    (void)in_sizes; (void)n_in; (void)out_size;
    const float* x  = (const float*)d_in[0];
    const float* Wq = (const float*)d_in[1];
    const float* bq = (const float*)d_in[2];
    const float* Wk = (const float*)d_in[3];
    const float* bk = (const float*)d_in[4];
    const float* Wv = (const float*)d_in[5];
    const float* bv = (const float*)d_in[6];
    float* out = (float*)d_out;

    cudaFuncSetAttribute(gemm_k<0>, cudaFuncAttributeMaxDynamicSharedMemorySize, SMEM_TOTAL);
    cudaFuncSetAttribute(gemm_k<1>, cudaFuncAttributeMaxDynamicSharedMemorySize, SMEM_TOTAL);
    cudaFuncSetAttribute(gemm_k<2>, cudaFuncAttributeMaxDynamicSharedMemorySize, SMEM_TOTAL);

    // 1) bf16 hi/lo splits
    k_split<<<(Mn * Hn + 255) / 256, 256>>>(x,  0, Mn * Hn);
    k_split<<<(Hn * Hn + 255) / 256, 256>>>(Wq, 1, Hn * Hn);
    k_split<<<(Hn * Hn + 255) / 256, 256>>>(Wk, 2, Hn * Hn);
    k_split<<<(Hn * Hn + 255) / 256, 256>>>(Wv, 3, Hn * Hn);

    // 2) fused QKV projection + bias + fp16 quantize (Q,K,V all [B,S,H])
    gemm_k<0><<<dim3(3 * Hn / BN, Mn / BM, 1), NT, SMEM_TOTAL>>>(bq, bk, bv, nullptr);

    // 3) scores = Q K^T / 32, fp16 quantize
    gemm_k<1><<<dim3(Sn / BN, Sn / BM, Bn), NT, SMEM_TOTAL>>>(nullptr, nullptr, nullptr, nullptr);

    // 4) softmax rows, fp16 quantize (in-place)
    k_softmax<<<Mn, 256>>>();

    // 5) out = attn @ V (f32), B operand from row-major V via ldmatrix.trans
    gemm_k<2><<<dim3(Hn / BN, Sn / BM, Bn), NT, SMEM_TOTAL>>>(nullptr, nullptr, nullptr, out);
}

// round 11
// speedup vs baseline: 1.1903x; 1.1657x over previous
#include <cuda_runtime.h>
#include <cuda_fp16.h>
#include <cuda_bf16.h>
#include <cstdint>
#include <cstddef>

// ---------------------------------------------------------------------------
// QuantizedAttention (B=4, S=2048, H=1024)
//   quantize() == IEEE fp16 RN-even -> fp16 dataflow; __float2half_rn is
//   bit-exact vs reference. QKV uses bf16 hi/lo split GEMM (hh+hl+lh,
//   K_eff=3072). R11 = R7's proven mainloop (wait<1> -> sync -> prefetch;
//   per-thread wait THEN cross-thread sync, order is load-bearing) plus:
//     - V stored naturally [B,S,H]; attn@V uses ldmatrix.trans (R8-validated)
//       -> no 2-byte stride-4KB scatter epilogue
//     - merged split kernel (1 launch)
//     - shuffle softmax, uint4 I/O, exact expf
//     - paired half2/float2 epilogue stores
// ---------------------------------------------------------------------------

namespace {
constexpr int Bn = 4, Sn = 2048, Hn = 1024, Mn = Bn * Sn;

constexpr int BM = 128, BN = 128, BK = 64;
constexpr int NS = 3;
constexpr int MAT_BYTES   = BM * BK * 2;        // 16 KB (A or B)
constexpr int STAGE_BYTES = 2 * MAT_BYTES;      // 32 KB
constexpr int SMEM_TOTAL  = NS * STAGE_BYTES;   // 96 KB dynamic (2 CTAs/SM)
}

// ---- scratch (device globals; allocation forbidden) -----------------------
__device__ __align__(16) uint16_t g_xhi[Mn * Hn];
__device__ __align__(16) uint16_t g_xlo[Mn * Hn];
__device__ __align__(16) uint16_t g_whi[3 * Hn * Hn];
__device__ __align__(16) uint16_t g_wlo[3 * Hn * Hn];
__device__ __align__(16) uint16_t g_q[Mn * Hn];       // fp16 [B,S,H]
__device__ __align__(16) uint16_t g_k[Mn * Hn];       // fp16 [B,S,H]
__device__ __align__(16) uint16_t g_v[Mn * Hn];       // fp16 [B,S,H] (natural)
__device__ __align__(16) uint16_t g_s[Bn * Sn * Sn];  // fp16 scores/probs

// ---- PTX helpers ----------------------------------------------------------
__device__ __forceinline__ uint32_t smem_u32(const void* p) {
    return (uint32_t)__cvta_generic_to_shared(p);
}
__device__ __forceinline__ void cp16(uint32_t s, const void* g) {
    asm volatile("cp.async.cg.shared.global [%0], [%1], 16;\n" :: "r"(s), "l"(g));
}
__device__ __forceinline__ void cp_commit() {
    asm volatile("cp.async.commit_group;\n" ::: "memory");
}
template <int N>
__device__ __forceinline__ void cp_wait() {
    asm volatile("cp.async.wait_group %0;\n" :: "n"(N) : "memory");
}
__device__ __forceinline__ void ldm_x4(uint32_t* r, uint32_t addr) {
    asm volatile("ldmatrix.sync.aligned.m8n8.x4.shared.b16 {%0,%1,%2,%3}, [%4];\n"
                 : "=r"(r[0]), "=r"(r[1]), "=r"(r[2]), "=r"(r[3]) : "r"(addr));
}
__device__ __forceinline__ void ldm_x4_t(uint32_t* r, uint32_t addr) {
    asm volatile("ldmatrix.sync.aligned.m8n8.x4.trans.shared.b16 {%0,%1,%2,%3}, [%4];\n"
                 : "=r"(r[0]), "=r"(r[1]), "=r"(r[2]), "=r"(r[3]) : "r"(addr));
}
template <bool BF16>
__device__ __forceinline__ void mma_16816(float* d, const uint32_t* a, const uint32_t* b) {
    if constexpr (BF16) {
        asm volatile(
            "mma.sync.aligned.m16n8k16.row.col.f32.bf16.bf16.f32 "
            "{%0,%1,%2,%3},{%4,%5,%6,%7},{%8,%9},{%0,%1,%2,%3};\n"
            : "+f"(d[0]), "+f"(d[1]), "+f"(d[2]), "+f"(d[3])
            : "r"(a[0]), "r"(a[1]), "r"(a[2]), "r"(a[3]), "r"(b[0]), "r"(b[1]));
    } else {
        asm volatile(
            "mma.sync.aligned.m16n8k16.row.col.f32.f16.f16.f32 "
            "{%0,%1,%2,%3},{%4,%5,%6,%7},{%8,%9},{%0,%1,%2,%3};\n"
            : "+f"(d[0]), "+f"(d[1]), "+f"(d[2]), "+f"(d[3])
            : "r"(a[0]), "r"(a[1]), "r"(a[2]), "r"(a[3]), "r"(b[0]), "r"(b[1]));
    }
}

// ---- merged split: f32 -> bf16 hi/lo for x, Wq, Wk, Wv --------------------
__global__ void k_split_all(const float* __restrict__ x,
                            const float* __restrict__ Wq,
                            const float* __restrict__ Wk,
                            const float* __restrict__ Wv) {
    int i = blockIdx.x * 256 + threadIdx.x;   // grid covers total exactly
    const float* src;
    uint16_t* hi;
    uint16_t* lo;
    int idx;
    if (i < Mn * Hn) {
        src = x; idx = i; hi = g_xhi; lo = g_xlo;
    } else {
        int r = i - Mn * Hn;
        int w = r >> 20;                       // Hn*Hn == 2^20
        idx = r & (Hn * Hn - 1);
        src = (w == 0) ? Wq : ((w == 1) ? Wk : Wv);
        hi = g_whi + w * Hn * Hn;
        lo = g_wlo + w * Hn * Hn;
    }
    float v = src[idx];
    __nv_bfloat16 h = __float2bfloat16(v);
    __nv_bfloat16 l = __float2bfloat16(v - __bfloat162float(h));
    hi[idx] = __bfloat16_as_ushort(h);
    lo[idx] = __bfloat16_as_ushort(l);
}

// ---- 128x128x64, 3-stage cp.async, mma.sync GEMM --------------------------
// MODE 0: QKV  (bf16 split, K_eff=3072: hh|hl|lh segments of 1024)
// MODE 1: scores = Q K^T * (1/32) -> fp16 g_s   (per batch)
// MODE 2: out    = attn @ V -> f32 (B from row-major V via ldm.trans)
template <int MODE>
__global__ __launch_bounds__(256, 2) void gemm_k(
    const float* __restrict__ bq, const float* __restrict__ bk,
    const float* __restrict__ bv, float* __restrict__ outF) {

    constexpr bool BF = (MODE == 0);
    constexpr int KT = (MODE == 0) ? 48 : ((MODE == 1) ? 16 : 32);  // K/64

    extern __shared__ __align__(128) uint16_t sh[];

    const int tid  = threadIdx.x;
    const int warp = tid >> 5;
    const int lane = tid & 31;
    const int wm = warp >> 2;             // 0..1 (64-row warp tiles)
    const int wn = warp & 3;              // 0..3 (32-col warp tiles)
    const int m0 = blockIdx.y * BM;
    const int n0 = blockIdx.x * BN;
    const int bz = blockIdx.z;

    const uint32_t shBase = smem_u32(sh);

    auto load_stage = [&](int j) {
        const uint32_t sA = shBase + (uint32_t)(j % NS) * STAGE_BYTES;
        const uint32_t sB = sA + (uint32_t)MAT_BYTES;
        const uint16_t* ap;
        const uint16_t* bp;
        int kin, lda;
        if constexpr (MODE == 0) {
            int seg = j >> 4;             // 0:hh 1:hl 2:lh (16 steps each)
            kin = (j & 15) * BK;
            ap = (seg < 2) ? g_xhi : g_xlo;
            bp = (seg == 1) ? g_wlo : g_whi;
            lda = Hn;
        } else if constexpr (MODE == 1) {
            kin = j * BK;
            ap = g_q + (size_t)bz * Sn * Hn;
            bp = g_k + (size_t)bz * Sn * Hn;
            lda = Hn;
        } else {
            kin = j * BK;
            ap = g_s + (size_t)bz * Sn * Sn;
            bp = g_v + (size_t)bz * Sn * Hn;
            lda = Sn;
        }
        // A: 128 rows x 8 chunks(16B), 128B rows, XOR swizzle
#pragma unroll
        for (int it = 0; it < 4; it++) {
            int i = tid + it * 256;
            int row = i >> 3, c = i & 7;
            cp16(sA + (uint32_t)(row * 128 + ((c ^ (row & 7)) << 4)),
                 ap + (size_t)(m0 + row) * lda + kin + c * 8);
        }
        if constexpr (MODE != 2) {
            // B: 128 n-rows x 8 chunks (k-contig), 128B rows
#pragma unroll
            for (int it = 0; it < 4; it++) {
                int i = tid + it * 256;
                int row = i >> 3, c = i & 7;
                cp16(sB + (uint32_t)(row * 128 + ((c ^ (row & 7)) << 4)),
                     bp + (size_t)(n0 + row) * Hn + kin + c * 8);
            }
        } else {
            // B: 64 k-rows x 16 chunks (n-contig), 256B rows
#pragma unroll
            for (int it = 0; it < 4; it++) {
                int i = tid + it * 256;
                int row = i >> 4, c = i & 15;
                cp16(sB + (uint32_t)(row * 256 + ((c ^ (row & 7)) << 4)),
                     bp + (size_t)(kin + row) * Hn + n0 + c * 8);
            }
        }
    };

    float acc[4][4][4];
#pragma unroll
    for (int a = 0; a < 4; a++)
#pragma unroll
        for (int b2 = 0; b2 < 4; b2++)
#pragma unroll
            for (int e = 0; e < 4; e++) acc[a][b2][e] = 0.f;

    load_stage(0); cp_commit();
    load_stage(1); cp_commit();

    for (int j = 0; j < KT; ++j) {
        cp_wait<1>();          // per-thread: group j complete (pending {j,j+1})
        __syncthreads();       // cross-thread visibility + stage reuse safety
        if (j + 2 < KT) load_stage(j + 2);
        cp_commit();

        const uint32_t aS = shBase + (uint32_t)(j % NS) * STAGE_BYTES;
        const uint32_t bS = aS + (uint32_t)MAT_BYTES;

#pragma unroll
        for (int kc = 0; kc < 4; kc++) {
            const int lc = kc * 2;
            uint32_t afr[4][4], bfr[2][4];
#pragma unroll
            for (int mi = 0; mi < 4; mi++) {
                int row = wm * 64 + mi * 16 + (lane & 15);
                int ch  = (lc + (lane >> 4)) ^ (row & 7);
                ldm_x4(afr[mi], aS + (uint32_t)(row * 128 + (ch << 4)));
            }
#pragma unroll
            for (int nj = 0; nj < 2; nj++) {
                if constexpr (MODE != 2) {
                    int nrow = wn * 32 + nj * 16 + ((lane & 7) + ((lane >> 4) << 3));
                    int ch   = (lc + ((lane >> 3) & 1)) ^ (nrow & 7);
                    ldm_x4(bfr[nj], bS + (uint32_t)(nrow * 128 + (ch << 4)));
                } else {
                    int krow = kc * 16 + (lane & 15);
                    int c    = ((wn * 32 + nj * 16) >> 3) + (lane >> 4);
                    ldm_x4_t(bfr[nj],
                             bS + (uint32_t)(krow * 256 + ((c ^ (krow & 7)) << 4)));
                }
            }
#pragma unroll
            for (int mi = 0; mi < 4; mi++)
#pragma unroll
                for (int ni = 0; ni < 4; ni++)
                    mma_16816<BF>(acc[mi][ni], afr[mi], &bfr[ni >> 1][(ni & 1) * 2]);
        }
    }

    // ---- epilogue (paired stores) ----
#pragma unroll
    for (int mi = 0; mi < 4; mi++)
#pragma unroll
        for (int ni = 0; ni < 4; ni++)
#pragma unroll
            for (int eh = 0; eh < 2; eh++) {
                const int r = m0 + wm * 64 + mi * 16 + (lane >> 2) + eh * 8;
                const int c = n0 + wn * 32 + ni * 8 + ((lane & 3) << 1);
                float y0 = acc[mi][ni][eh * 2];
                float y1 = acc[mi][ni][eh * 2 + 1];
                if constexpr (MODE == 0) {
                    const int which = c >> 10;           // 0:Q 1:K 2:V
                    const int o = c & (Hn - 1);
                    const float* bias = (which == 0) ? bq : ((which == 1) ? bk : bv);
                    uint16_t* base = (which == 0) ? g_q : ((which == 1) ? g_k : g_v);
                    __half2 h2 = __floats2half2_rn(y0 + __ldg(&bias[o]),
                                                   y1 + __ldg(&bias[o + 1]));
                    *reinterpret_cast<uint32_t*>(base + (size_t)r * Hn + o) =
                        *reinterpret_cast<uint32_t*>(&h2);
                } else if constexpr (MODE == 1) {
                    __half2 h2 = __floats2half2_rn(y0 * 0.03125f, y1 * 0.03125f);
                    *reinterpret_cast<uint32_t*>(
                        g_s + (size_t)bz * Sn * Sn + (size_t)r * Sn + c) =
                        *reinterpret_cast<uint32_t*>(&h2);
                } else {
                    *reinterpret_cast<float2*>(
                        outF + ((size_t)bz * Sn + r) * Hn + c) = make_float2(y0, y1);
                }
            }
}

// ---- row softmax over 2048 fp16 scores, fp16-RN in-place ------------------
// 256 threads, 8 halfs per thread (one uint4), warp-shuffle reductions.
__global__ void k_softmax(void) {
    const int row  = blockIdx.x;
    const int tid  = threadIdx.x;
    const int wid  = tid >> 5;
    const int lane = tid & 31;
    uint4* p = reinterpret_cast<uint4*>(g_s + (size_t)row * Sn);

    uint4 u = p[tid];
    float v[8];
    {
        v[0] = __half2float(__ushort_as_half((unsigned short)(u.x & 0xFFFFu)));
        v[1] = __half2float(__ushort_as_half((unsigned short)(u.x >> 16)));
        v[2] = __half2float(__ushort_as_half((unsigned short)(u.y & 0xFFFFu)));
        v[3] = __half2float(__ushort_as_half((unsigned short)(u.y >> 16)));
        v[4] = __half2float(__ushort_as_half((unsigned short)(u.z & 0xFFFFu)));
        v[5] = __half2float(__ushort_as_half((unsigned short)(u.z >> 16)));
        v[6] = __half2float(__ushort_as_half((unsigned short)(u.w & 0xFFFFu)));
        v[7] = __half2float(__ushort_as_half((unsigned short)(u.w >> 16)));
    }

    __shared__ float smA[8], smB[8];

    float mx = v[0];
#pragma unroll
    for (int i = 1; i < 8; i++) mx = fmaxf(mx, v[i]);
#pragma unroll
    for (int o = 16; o > 0; o >>= 1) mx = fmaxf(mx, __shfl_xor_sync(0xFFFFFFFFu, mx, o));
    if (lane == 0) smA[wid] = mx;
    __syncthreads();
    if (wid == 0) {
        float t = (lane < 8) ? smA[lane] : -3.4e38f;
#pragma unroll
        for (int o = 4; o > 0; o >>= 1) t = fmaxf(t, __shfl_xor_sync(0xFFFFFFFFu, t, o));
        if (lane == 0) smA[0] = t;
    }
    __syncthreads();
    mx = smA[0];

    float sum = 0.f;
#pragma unroll
    for (int i = 0; i < 8; i++) { v[i] = expf(v[i] - mx); sum += v[i]; }
#pragma unroll
    for (int o = 16; o > 0; o >>= 1) sum += __shfl_xor_sync(0xFFFFFFFFu, sum, o);
    if (lane == 0) smB[wid] = sum;
    __syncthreads();
    if (wid == 0) {
        float t = (lane < 8) ? smB[lane] : 0.f;
#pragma unroll
        for (int o = 4; o > 0; o >>= 1) t += __shfl_xor_sync(0xFFFFFFFFu, t, o);
        if (lane == 0) smB[0] = t;
    }
    __syncthreads();
    const float inv = 1.0f / smB[0];

    uint32_t r[4];
#pragma unroll
    for (int i = 0; i < 4; i++) {
        __half2 h2 = __floats2half2_rn(v[2 * i] * inv, v[2 * i + 1] * inv);
        r[i] = *reinterpret_cast<uint32_t*>(&h2);
    }
    p[tid] = make_uint4(r[0], r[1], r[2], r[3]);
}

// ---------------------------------------------------------------------------
extern "C" void kernel_launch(void* const* d_in, const int* in_sizes, int n_in,
                              void* d_out, int out_size) {
    (void)in_sizes; (void)n_in; (void)out_size;
    const float* x  = (const float*)d_in[0];
    const float* Wq = (const float*)d_in[1];
    const float* bq = (const float*)d_in[2];
    const float* Wk = (const float*)d_in[3];
    const float* bk = (const float*)d_in[4];
    const float* Wv = (const float*)d_in[5];
    const float* bv = (const float*)d_in[6];
    float* out = (float*)d_out;

    cudaFuncSetAttribute(gemm_k<0>, cudaFuncAttributeMaxDynamicSharedMemorySize, SMEM_TOTAL);
    cudaFuncSetAttribute(gemm_k<1>, cudaFuncAttributeMaxDynamicSharedMemorySize, SMEM_TOTAL);
    cudaFuncSetAttribute(gemm_k<2>, cudaFuncAttributeMaxDynamicSharedMemorySize, SMEM_TOTAL);

    // 1) bf16 hi/lo splits (single merged launch)
    k_split_all<<<(Mn * Hn + 3 * Hn * Hn) / 256, 256>>>(x, Wq, Wk, Wv);

    // 2) fused QKV projection + bias + fp16 quantize (Q,K,V all [B,S,H])
    gemm_k<0><<<dim3(3 * Hn / BN, Mn / BM, 1), 256, SMEM_TOTAL>>>(bq, bk, bv, nullptr);

    // 3) scores = Q K^T / 32, fp16 quantize
    gemm_k<1><<<dim3(Sn / BN, Sn / BM, Bn), 256, SMEM_TOTAL>>>(nullptr, nullptr, nullptr, nullptr);

    // 4) softmax rows, fp16 quantize (in-place)
    k_softmax<<<Mn, 256>>>();

    // 5) out = attn @ V (f32), B operand from row-major V via ldmatrix.trans
    gemm_k<2><<<dim3(Hn / BN, Sn / BM, Bn), 256, SMEM_TOTAL>>>(nullptr, nullptr, nullptr, out);
}